// round 16
// baseline (speedup 1.0000x reference)
#include <cuda_runtime.h>
#include <cuda_fp16.h>
#include <cstdint>

// ---------------------------------------------------------------------------
// DynamicPerceiverAttention  (B=8 T=4 N1=1024 N2=64 D=1024 H=16 DH=64)
// Legacy tensor path (mma.sync fp16) — tcgen05 rejected by compute_103 PTX.
//
// R16: gemm_h pair-granularity pipeline (barriers 32 -> 16 per CTA);
//      attention K/V via 2-stage cp.async ring with zero-fill masking.
// ---------------------------------------------------------------------------

#define BB    8
#define TT    4
#define NN1   1024
#define NN2   64
#define DD    1024
#define HH    16
#define DHH   64
#define INNER 1024
#define NBT   32
#define NK    1025
#define MKV_PAD 32896   // 257*128
#define MQ    2048

__device__ __half g_Akv_h  [(size_t)MKV_PAD * DD];
__device__ __half g_KV_h   [(size_t)MKV_PAD * 2048];
__device__ float  g_ln     [(size_t)MQ * DD];
__device__ __half g_lnr_h  [(size_t)MQ * DD];
__device__ __half g_Q_h    [(size_t)MQ * INNER];
__device__ __half g_O_h    [(size_t)MQ * INNER];
__device__ __half g_WkvT_h [(size_t)2048 * 1024];
__device__ __half g_WqT_h  [(size_t)1024 * 1024];
__device__ __half g_WoutT_h[(size_t)1024 * 1024];
__device__ float  g_dw     [NBT * HH];

__device__ __forceinline__ uint32_t smem_u32(const void* p)
{
    uint32_t a;
    asm("{ .reg .u64 t; cvta.to.shared.u64 t, %1; cvt.u32.u64 %0, t; }"
        : "=r"(a) : "l"(p));
    return a;
}

#define MMA_F16(d, a, b) \
    asm volatile( \
        "mma.sync.aligned.m16n8k16.row.col.f32.f16.f16.f32 " \
        "{%0,%1,%2,%3},{%4,%5,%6,%7},{%8,%9},{%0,%1,%2,%3};\n" \
        : "+f"((d)[0]), "+f"((d)[1]), "+f"((d)[2]), "+f"((d)[3]) \
        : "r"((a)[0]), "r"((a)[1]), "r"((a)[2]), "r"((a)[3]), \
          "r"((b)[0]), "r"((b)[1]))

#define MMA_F16B(d, a, b0, b1) \
    asm volatile( \
        "mma.sync.aligned.m16n8k16.row.col.f32.f16.f16.f32 " \
        "{%0,%1,%2,%3},{%4,%5,%6,%7},{%8,%9},{%0,%1,%2,%3};\n" \
        : "+f"((d)[0]), "+f"((d)[1]), "+f"((d)[2]), "+f"((d)[3]) \
        : "r"((a)[0]), "r"((a)[1]), "r"((a)[2]), "r"((a)[3]), \
          "r"(b0), "r"(b1))

#define LDMX4(r, addr) \
    asm volatile("ldmatrix.sync.aligned.m8n8.x4.shared.b16 {%0,%1,%2,%3}, [%4];" \
                 : "=r"((r)[0]), "=r"((r)[1]), "=r"((r)[2]), "=r"((r)[3]) \
                 : "r"(addr))

// ---------------------------------------------------------------------------
// LayerNorm (one 256-thread block per 1024-float row)
// ---------------------------------------------------------------------------
template<int MODE>
__global__ void ln_kernel(const float* __restrict__ in,
                          const float* __restrict__ gamma,
                          const float* __restrict__ beta)
{
    __shared__ float red[16];
    __shared__ float mu_s, rs_s;

    const int r   = blockIdx.x;
    const int tid = threadIdx.x;

    float4 v = reinterpret_cast<const float4*>(in + (size_t)r * DD)[tid];
    float s = v.x + v.y + v.z + v.w;
    float q = v.x * v.x + v.y * v.y + v.z * v.z + v.w * v.w;
#pragma unroll
    for (int o = 16; o > 0; o >>= 1) {
        s += __shfl_down_sync(0xffffffffu, s, o);
        q += __shfl_down_sync(0xffffffffu, q, o);
    }
    const int wid = tid >> 5;
    if ((tid & 31) == 0) { red[wid] = s; red[8 + wid] = q; }
    __syncthreads();
    if (tid == 0) {
        float ss = 0.f, qq = 0.f;
#pragma unroll
        for (int i = 0; i < 8; i++) { ss += red[i]; qq += red[8 + i]; }
        float mu  = ss * (1.0f / DD);
        float var = qq * (1.0f / DD) - mu * mu;
        mu_s = mu;
        rs_s = rsqrtf(var + 1e-5f);
    }
    __syncthreads();
    const float mu = mu_s, rs = rs_s;

    float4 gv = reinterpret_cast<const float4*>(gamma)[tid];
    float4 bv = reinterpret_cast<const float4*>(beta)[tid];
    float4 o;
    o.x = (v.x - mu) * rs * gv.x + bv.x;
    o.y = (v.y - mu) * rs * gv.y + bv.y;
    o.z = (v.z - mu) * rs * gv.z + bv.z;
    o.w = (v.w - mu) * rs * gv.w + bv.w;

    const __half2 h01 = __floats2half2_rn(o.x, o.y);
    const __half2 h23 = __floats2half2_rn(o.z, o.w);

    if (MODE == 1) {
        const int bt = r >> 10, i = r & 1023;
        __half2* d = reinterpret_cast<__half2*>(
            g_Akv_h + ((size_t)bt * NK + i) * DD) + 2 * tid;
        d[0] = h01; d[1] = h23;
    } else {
        reinterpret_cast<float4*>(g_ln + (size_t)r * DD)[tid] = o;
        __half2* dl = reinterpret_cast<__half2*>(g_lnr_h + (size_t)r * DD) + 2 * tid;
        dl[0] = h01; dl[1] = h23;
        const int bt = r >> 6, i = r & 63;
        if (i == 0) {
            __half2* da = reinterpret_cast<__half2*>(
                g_Akv_h + ((size_t)bt * NK + NN1) * DD) + 2 * tid;
            da[0] = h01; da[1] = h23;
        }
    }
}

// ---------------------------------------------------------------------------
// Transpose + fp16 convert (+scale): WT[n][k] = half(W[k][n] * scale)
// ---------------------------------------------------------------------------
__global__ void transpose_h(const float* __restrict__ W, __half* __restrict__ WT,
                            int Kd, int Nd, float scale)
{
    __shared__ float tile[32][33];
    const int n0 = blockIdx.x * 32, k0 = blockIdx.y * 32;
    const int tx = threadIdx.x, ty = threadIdx.y;
#pragma unroll
    for (int i = 0; i < 32; i += 8)
        tile[ty + i][tx] = W[(size_t)(k0 + ty + i) * Nd + n0 + tx];
    __syncthreads();
#pragma unroll
    for (int i = 0; i < 32; i += 8)
        WT[(size_t)(n0 + ty + i) * Kd + k0 + tx] =
            __float2half_rn(tile[tx][ty + i] * scale);
}

// ---------------------------------------------------------------------------
// fp16 GEMM: C[M,N] = A[M,K] * Bt[N,K]^T  (fp32 acc, OutT output)
// CTA 128x128, 256 thr, mma.m16n8k16, 4-stage cp.async ring with PAIR
// granularity (one wait+barrier per 2 chunks), ldmatrix.x4 frag loads
// double-buffered across kk-phases.
// ---------------------------------------------------------------------------
#define HCH   32
#define STG_BYTES (2 * 128 * 40 * 2)     // 20480 B
#define GEMM_H_SMEM (4 * STG_BYTES)      // 81920 B

template<typename OutT>
__global__ __launch_bounds__(256, 2)
void gemm_h(const __half* __restrict__ A, const __half* __restrict__ Bt,
            OutT* __restrict__ C, int M, int N, int K)
{
    extern __shared__ __half sh[];
    const uint32_t sb = smem_u32(sh);

    const int tid  = threadIdx.x;
    const int lane = tid & 31, warp = tid >> 5;
    const int g    = lane >> 2, tig = lane & 3;
    const int wm   = warp >> 2, wn = warp & 3;
    const int bm0  = blockIdx.y * 128, bn0 = blockIdx.x * 128;

    const int r0  = tid >> 2;
    const int sg0 = tid & 3;
    const __half* a_src = A  + (size_t)(bm0 + r0) * K + sg0 * 8;
    const __half* b_src = Bt + (size_t)(bn0 + r0) * K + sg0 * 8;
    const size_t rstep = (size_t)64 * K;
    const uint32_t soff = (uint32_t)(r0 * 80 + sg0 * 16);

    // ldmatrix lane offsets (bytes), rows are 80 B apart
    const uint32_t a_lm = (uint32_t)((wm * 64 + ((lane >> 3) & 1) * 8 + (lane & 7)) * 80
                                     + (lane >> 4) * 16);
    const uint32_t b_lm = (uint32_t)(128 * 80
                                     + (wn * 32 + ((lane >> 4) & 1) * 8 + (lane & 7)) * 80
                                     + ((lane >> 3) & 1) * 16);

    const int nch   = K / HCH;
    const int npair = nch / 2;

    auto load_chunk = [&](int c, int s) {
        const uint32_t abase = sb + s * STG_BYTES;
        const uint32_t bbase = abase + 128 * 80;
        const __half* ap = a_src + c * HCH;
        const __half* bp = b_src + c * HCH;
        asm volatile("cp.async.cg.shared.global [%0], [%1], 16;"
                     :: "r"(abase + soff),           "l"((const void*)ap) : "memory");
        asm volatile("cp.async.cg.shared.global [%0], [%1], 16;"
                     :: "r"(abase + soff + 64 * 80), "l"((const void*)(ap + rstep)) : "memory");
        asm volatile("cp.async.cg.shared.global [%0], [%1], 16;"
                     :: "r"(bbase + soff),           "l"((const void*)bp) : "memory");
        asm volatile("cp.async.cg.shared.global [%0], [%1], 16;"
                     :: "r"(bbase + soff + 64 * 80), "l"((const void*)(bp + rstep)) : "memory");
    };
    auto load_pair = [&](int p) {
        load_chunk(2 * p,     (2 * p) & 3);
        load_chunk(2 * p + 1, (2 * p + 1) & 3);
        asm volatile("cp.async.commit_group;" ::: "memory");
    };

    uint32_t af0[4][4], bf0[2][4];
    uint32_t af1[4][4], bf1[2][4];

    auto load_frags = [&](uint32_t stage, uint32_t koff,
                          uint32_t af[4][4], uint32_t bf[2][4]) {
#pragma unroll
        for (int mt = 0; mt < 4; mt++)
            LDMX4(af[mt], stage + a_lm + mt * 1280 + koff);
#pragma unroll
        for (int ntp = 0; ntp < 2; ntp++)
            LDMX4(bf[ntp], stage + b_lm + ntp * 1280 + koff);
    };

    float acc[4][4][4];
#pragma unroll
    for (int a = 0; a < 4; a++)
#pragma unroll
        for (int b = 0; b < 4; b++)
#pragma unroll
            for (int d = 0; d < 4; d++) acc[a][b][d] = 0.f;

    // prologue: pairs 0 and 1 in flight; wait pair 0; preload chunk-0 kk0 frags
    load_pair(0);
    load_pair(1);
    asm volatile("cp.async.wait_group 1;" ::: "memory");
    __syncthreads();
    load_frags(sb, 0, af0, bf0);

#define MMA_TILE(afv, bfv) \
    _Pragma("unroll") \
    for (int mt = 0; mt < 4; mt++) \
        _Pragma("unroll") \
        for (int nt = 0; nt < 4; nt++) \
            MMA_F16B(acc[mt][nt], afv[mt], \
                     bfv[nt >> 1][2 * (nt & 1)], bfv[nt >> 1][2 * (nt & 1) + 1]);

    for (int p = 0; p < npair; p++) {
        const uint32_t sa = sb + ((2 * p) & 3) * STG_BYTES;
        const uint32_t sbg = sb + ((2 * p + 1) & 3) * STG_BYTES;

        load_frags(sa, 32, af1, bf1);      // chunk 2p   kk1
        MMA_TILE(af0, bf0);                // chunk 2p   kk0
        load_frags(sbg, 0, af0, bf0);      // chunk 2p+1 kk0
        MMA_TILE(af1, bf1);                // chunk 2p   kk1
        load_frags(sbg, 32, af1, bf1);     // chunk 2p+1 kk1
        MMA_TILE(af0, bf0);                // chunk 2p+1 kk0
        MMA_TILE(af1, bf1);                // chunk 2p+1 kk1

        if (p + 1 < npair) {
            asm volatile("cp.async.wait_group 0;" ::: "memory");  // pair p+1 done
            __syncthreads();   // publish pair p+1; all reads of pair p's stages done
            if (p + 2 < npair) load_pair(p + 2);
            load_frags(sb + ((2 * p + 2) & 3) * STG_BYTES, 0, af0, bf0);
        }
    }
#undef MMA_TILE

#pragma unroll
    for (int mt = 0; mt < 4; mt++) {
        const int row = bm0 + wm * 64 + mt * 16 + g;
#pragma unroll
        for (int nt = 0; nt < 4; nt++) {
            const int col = bn0 + wn * 32 + nt * 8 + 2 * tig;
            if constexpr (sizeof(OutT) == 4) {
                *reinterpret_cast<float2*>((float*)C + (size_t)row * N + col) =
                    make_float2(acc[mt][nt][0], acc[mt][nt][1]);
                *reinterpret_cast<float2*>((float*)C + (size_t)(row + 8) * N + col) =
                    make_float2(acc[mt][nt][2], acc[mt][nt][3]);
            } else {
                *reinterpret_cast<__half2*>((__half*)C + (size_t)row * N + col) =
                    __floats2half2_rn(acc[mt][nt][0], acc[mt][nt][1]);
                *reinterpret_cast<__half2*>((__half*)C + (size_t)(row + 8) * N + col) =
                    __floats2half2_rn(acc[mt][nt][2], acc[mt][nt][3]);
            }
        }
    }
}

// ---------------------------------------------------------------------------
// dw = softmax(relu(mean(ln) @ Wd1 + bd1) @ Wd2 + bd2)
// ---------------------------------------------------------------------------
__global__ __launch_bounds__(256)
void dw_kernel(const float* __restrict__ Wd1, const float* __restrict__ bd1,
               const float* __restrict__ Wd2, const float* __restrict__ bd2)
{
    __shared__ float mean_s[1024];
    __shared__ float hid_s[256];
    const int bt  = blockIdx.x;
    const int tid = threadIdx.x;

    for (int d = tid; d < 1024; d += 256) {
        float s = 0.f;
#pragma unroll 4
        for (int r = 0; r < 64; r++)
            s += g_ln[((size_t)bt * 64 + r) * DD + d];
        mean_s[d] = s * (1.0f / 64.0f);
    }
    __syncthreads();

    float hsum = bd1[tid];
    for (int dd = 0; dd < 1024; dd++)
        hsum = fmaf(mean_s[dd], Wd1[dd * 256 + tid], hsum);
    hid_s[tid] = fmaxf(hsum, 0.f);
    __syncthreads();

    if (tid < 16) {
        float lg = bd2[tid];
        for (int j = 0; j < 256; j++)
            lg = fmaf(hid_s[j], Wd2[j * 16 + tid], lg);
        float mx = lg;
#pragma unroll
        for (int o = 8; o > 0; o >>= 1)
            mx = fmaxf(mx, __shfl_xor_sync(0x0000ffffu, mx, o));
        float e = expf(lg - mx);
        float ssum = e;
#pragma unroll
        for (int o = 8; o > 0; o >>= 1)
            ssum += __shfl_xor_sync(0x0000ffffu, ssum, o);
        g_dw[bt * HH + tid] = e / ssum;
    }
}

// ---------------------------------------------------------------------------
// Attention (tensor-core): one block per (bt,h), 128 threads (4 warps).
// K/V via 2-stage cp.async ring; masked tail keys zero-filled (then re-masked
// to -1e30, bit-identical to the blocking-load version).
// ---------------------------------------------------------------------------
#define AST 88                                   // smem stride in halves
#define QSZ (64 * AST)
#define KVSTG (2 * 64 * AST)                     // K + V per stage (halves)
#define ATTN_SMEM ((QSZ + 2 * KVSTG) * 2)        // 56320 B
#define LOG2E 1.4426950408889634f

__global__ __launch_bounds__(128)
void attn_kernel()
{
    extern __shared__ __half smh[];
    __half* Qs = smh;

    const int bt   = blockIdx.x >> 4;
    const int h    = blockIdx.x & 15;
    const int tid  = threadIdx.x;
    const int warp = tid >> 5, lane = tid & 31;
    const int g    = lane >> 2, tig = lane & 3;

    const uint32_t smb = smem_u32(smh);

    // async K/V chunk load into stage st (zero-fill beyond nk)
    auto load_kv = [&](int ch, int st) {
        const uint32_t ks = smb + (QSZ + st * KVSTG) * 2;
        const uint32_t vs = ks + 64 * AST * 2;
#pragma unroll
        for (int i = 0; i < 4; i++) {
            const int seg = tid + i * 128;
            const int j = seg >> 3, s = seg & 7;
            const int key = ch * 64 + j;
            const uint32_t nbytes = (key < NK) ? 16u : 0u;
            const int keyc = (key < NK) ? key : (NK - 1);
            const __half* kb = g_KV_h + ((size_t)bt * NK + keyc) * 2048
                             + h * DHH + s * 8;
            const uint32_t doff = (uint32_t)(j * AST + s * 8) * 2;
            asm volatile("cp.async.cg.shared.global [%0], [%1], 16, %2;"
                         :: "r"(ks + doff), "l"((const void*)kb), "r"(nbytes)
                         : "memory");
            asm volatile("cp.async.cg.shared.global [%0], [%1], 16, %2;"
                         :: "r"(vs + doff), "l"((const void*)(kb + INNER)), "r"(nbytes)
                         : "memory");
        }
        asm volatile("cp.async.commit_group;" ::: "memory");
    };

    // start chunk 0 early
    load_kv(0, 0);

    // load Q tile (64 x 64 fp16, pre-scaled via Wq)
#pragma unroll
    for (int i = 0; i < 4; i++) {
        const int seg = tid + i * 128;
        const int r = seg >> 3, s = seg & 7;
        uint4 v = *reinterpret_cast<const uint4*>(
            g_Q_h + ((size_t)bt * 64 + r) * INNER + h * DHH + s * 8);
        *reinterpret_cast<uint4*>(Qs + r * AST + s * 8) = v;
    }
    __syncthreads();

    // persistent Q A-fragments
    uint32_t qa[4][4];
    {
        const __half* q0 = Qs + (warp * 16 + g) * AST;
        const __half* q1 = q0 + 8 * AST;
#pragma unroll
        for (int u = 0; u < 4; u++) {
            const int k0 = u * 16 + 2 * tig;
            qa[u][0] = *reinterpret_cast<const uint32_t*>(q0 + k0);
            qa[u][1] = *reinterpret_cast<const uint32_t*>(q1 + k0);
            qa[u][2] = *reinterpret_cast<const uint32_t*>(q0 + k0 + 8);
            qa[u][3] = *reinterpret_cast<const uint32_t*>(q1 + k0 + 8);
        }
    }

    float acc[8][4];
#pragma unroll
    for (int d = 0; d < 8; d++)
#pragma unroll
        for (int j = 0; j < 4; j++) acc[d][j] = 0.f;
    float m0 = -1e30f, m1 = -1e30f, l0 = 0.f, l1 = 0.f;

    for (int ch = 0; ch < 17; ch++) {
        __syncthreads();   // prior iteration's K/V reads done before overwrite
        if (ch + 1 < 17) load_kv(ch + 1, (ch + 1) & 1);
        if (ch + 1 < 17)
            asm volatile("cp.async.wait_group 1;" ::: "memory");
        else
            asm volatile("cp.async.wait_group 0;" ::: "memory");
        __syncthreads();   // publish chunk ch

        __half* Ks = smh + QSZ + (ch & 1) * KVSTG;
        __half* Vs = Ks + 64 * AST;

        // S = Q @ K^T
        float sf[8][4];
#pragma unroll
        for (int t = 0; t < 8; t++) {
            sf[t][0] = sf[t][1] = sf[t][2] = sf[t][3] = 0.f;
            const __half* kr = Ks + (t * 8 + g) * AST + 2 * tig;
#pragma unroll
            for (int u = 0; u < 4; u++) {
                uint32_t bfr[2];
                bfr[0] = *reinterpret_cast<const uint32_t*>(kr + u * 16);
                bfr[1] = *reinterpret_cast<const uint32_t*>(kr + u * 16 + 8);
                MMA_F16(sf[t], qa[u], bfr);
            }
        }

        if (ch * 64 + 64 > NK) {
#pragma unroll
            for (int t = 0; t < 8; t++) {
                const int k0 = ch * 64 + t * 8 + 2 * tig;
                if (k0 >= NK)     { sf[t][0] = -1e30f; sf[t][2] = -1e30f; }
                if (k0 + 1 >= NK) { sf[t][1] = -1e30f; sf[t][3] = -1e30f; }
            }
        }

        // online softmax
        float mx0 = -1e30f, mx1 = -1e30f;
#pragma unroll
        for (int t = 0; t < 8; t++) {
            mx0 = fmaxf(mx0, fmaxf(sf[t][0], sf[t][1]));
            mx1 = fmaxf(mx1, fmaxf(sf[t][2], sf[t][3]));
        }
        mx0 = fmaxf(mx0, __shfl_xor_sync(0xffffffffu, mx0, 1));
        mx0 = fmaxf(mx0, __shfl_xor_sync(0xffffffffu, mx0, 2));
        mx1 = fmaxf(mx1, __shfl_xor_sync(0xffffffffu, mx1, 1));
        mx1 = fmaxf(mx1, __shfl_xor_sync(0xffffffffu, mx1, 2));

        const float mn0 = fmaxf(m0, mx0), mn1 = fmaxf(m1, mx1);
        const float corr0 = __expf(m0 - mn0), corr1 = __expf(m1 - mn1);
        m0 = mn0; m1 = mn1;

        uint32_t pa[8], pb[8];
        float sum0 = 0.f, sum1 = 0.f;
#pragma unroll
        for (int t = 0; t < 8; t++) {
            __half2 p01 = h2exp2(__floats2half2_rn((sf[t][0] - mn0) * LOG2E,
                                                   (sf[t][1] - mn0) * LOG2E));
            __half2 p23 = h2exp2(__floats2half2_rn((sf[t][2] - mn1) * LOG2E,
                                                   (sf[t][3] - mn1) * LOG2E));
            pa[t] = *reinterpret_cast<uint32_t*>(&p01);
            pb[t] = *reinterpret_cast<uint32_t*>(&p23);
            float2 f01 = __half22float2(p01);
            float2 f23 = __half22float2(p23);
            sum0 += f01.x + f01.y;
            sum1 += f23.x + f23.y;
        }
        sum0 += __shfl_xor_sync(0xffffffffu, sum0, 1);
        sum0 += __shfl_xor_sync(0xffffffffu, sum0, 2);
        sum1 += __shfl_xor_sync(0xffffffffu, sum1, 1);
        sum1 += __shfl_xor_sync(0xffffffffu, sum1, 2);
        l0 = l0 * corr0 + sum0;
        l1 = l1 * corr1 + sum1;

#pragma unroll
        for (int d = 0; d < 8; d++) {
            acc[d][0] *= corr0; acc[d][1] *= corr0;
            acc[d][2] *= corr1; acc[d][3] *= corr1;
        }

        // O += P @ V
#pragma unroll
        for (int u = 0; u < 4; u++) {
            uint32_t pf[4] = { pa[2 * u], pb[2 * u], pa[2 * u + 1], pb[2 * u + 1] };
            const uint32_t vaddr = smem_u32(Vs + (u * 16 + (lane & 15)) * AST);
#pragma unroll
            for (int d = 0; d < 8; d++) {
                uint32_t bfr[2];
                asm volatile(
                    "ldmatrix.sync.aligned.m8n8.x2.trans.shared.b16 {%0,%1}, [%2];"
                    : "=r"(bfr[0]), "=r"(bfr[1]) : "r"(vaddr + d * 16));
                MMA_F16(acc[d], pf, bfr);
            }
        }
    }

    const float dwv = g_dw[bt * HH + h];
    const float sc0 = dwv / l0, sc1 = dwv / l1;
    const size_t row0 = (size_t)bt * 64 + warp * 16 + g;
#pragma unroll
    for (int d = 0; d < 8; d++) {
        const int col = h * DHH + d * 8 + 2 * tig;
        *reinterpret_cast<__half2*>(g_O_h + row0 * INNER + col) =
            __floats2half2_rn(acc[d][0] * sc0, acc[d][1] * sc0);
        *reinterpret_cast<__half2*>(g_O_h + (row0 + 8) * INNER + col) =
            __floats2half2_rn(acc[d][2] * sc1, acc[d][3] * sc1);
    }
}

// ---------------------------------------------------------------------------
extern "C" void kernel_launch(void* const* d_in, const int* in_sizes, int n_in,
                              void* d_out, int out_size)
{
    const float* x       = (const float*)d_in[0];
    const float* latents = (const float*)d_in[1];
    const float* gm      = (const float*)d_in[2];
    const float* bm      = (const float*)d_in[3];
    const float* gl      = (const float*)d_in[4];
    const float* bl      = (const float*)d_in[5];
    const float* Wq      = (const float*)d_in[6];
    const float* Wkv     = (const float*)d_in[7];
    const float* Wout    = (const float*)d_in[8];
    const float* Wd1     = (const float*)d_in[9];
    const float* bd1     = (const float*)d_in[10];
    const float* Wd2     = (const float*)d_in[11];
    const float* bd2     = (const float*)d_in[12];
    float* out = (float*)d_out;

    cudaFuncSetAttribute(gemm_h<__half>,
        cudaFuncAttributeMaxDynamicSharedMemorySize, GEMM_H_SMEM);
    cudaFuncSetAttribute(gemm_h<float>,
        cudaFuncAttributeMaxDynamicSharedMemorySize, GEMM_H_SMEM);
    cudaFuncSetAttribute(attn_kernel,
        cudaFuncAttributeMaxDynamicSharedMemorySize, ATTN_SMEM);

    __half *p_Akv, *p_lnr, *p_Q, *p_O, *p_KV, *p_WkvT, *p_WqT, *p_WoutT;
    cudaGetSymbolAddress((void**)&p_Akv,   g_Akv_h);
    cudaGetSymbolAddress((void**)&p_lnr,   g_lnr_h);
    cudaGetSymbolAddress((void**)&p_Q,     g_Q_h);
    cudaGetSymbolAddress((void**)&p_O,     g_O_h);
    cudaGetSymbolAddress((void**)&p_KV,    g_KV_h);
    cudaGetSymbolAddress((void**)&p_WkvT,  g_WkvT_h);
    cudaGetSymbolAddress((void**)&p_WqT,   g_WqT_h);
    cudaGetSymbolAddress((void**)&p_WoutT, g_WoutT_h);

    // Order keeps kv GEMM at ncu's profiled launch slot (index 3).
    transpose_h<<<dim3(64, 32), dim3(32, 8)>>>(Wkv,  p_WkvT,  1024, 2048, 1.0f);
    ln_kernel<1><<<BB * TT * NN1, 256>>>(x, gm, bm);
    ln_kernel<0><<<BB * TT * NN2, 256>>>(latents, gl, bl);

    // KV = Akv @ Wkv   (fp16 out)
    gemm_h<__half><<<dim3(16, MKV_PAD / 128), 256, GEMM_H_SMEM>>>(
        p_Akv, p_WkvT, p_KV, MKV_PAD, 2048, 1024);

    transpose_h<<<dim3(32, 32), dim3(32, 8)>>>(Wq,   p_WqT,   1024, 1024, 0.125f);
    transpose_h<<<dim3(32, 32), dim3(32, 8)>>>(Wout, p_WoutT, 1024, 1024, 1.0f);

    // Q = lnr @ (0.125*Wq)  (fp16 out)
    gemm_h<__half><<<dim3(8, 16), 256, GEMM_H_SMEM>>>(
        p_lnr, p_WqT, p_Q, MQ, 1024, 1024);

    // dynamic head weights
    dw_kernel<<<NBT, 256>>>(Wd1, bd1, Wd2, bd2);

    // attention (tensor cores)
    attn_kernel<<<NBT * HH, 128, ATTN_SMEM>>>();

    // out = O @ Wout   (fp32 out)
    gemm_h<float><<<dim3(8, 16), 256, GEMM_H_SMEM>>>(
        p_O, p_WoutT, out, MQ, 1024, 1024);
}

// round 17
// speedup vs baseline: 1.0613x; 1.0613x over previous
#include <cuda_runtime.h>
#include <cuda_fp16.h>
#include <cstdint>

// ---------------------------------------------------------------------------
// DynamicPerceiverAttention  (B=8 T=4 N1=1024 N2=64 D=1024 H=16 DH=64)
// Legacy tensor path (mma.sync fp16) — tcgen05 rejected by compute_103 PTX.
//
// R17: gemm_h reverted to R15 chunk-granularity pipeline (R16 pair version
//      regressed: regs 128, tensor 52.9%). Attention keeps the R16 2-stage
//      cp.async K/V ring (isolated for attribution).
// ---------------------------------------------------------------------------

#define BB    8
#define TT    4
#define NN1   1024
#define NN2   64
#define DD    1024
#define HH    16
#define DHH   64
#define INNER 1024
#define NBT   32
#define NK    1025
#define MKV_PAD 32896   // 257*128
#define MQ    2048

__device__ __half g_Akv_h  [(size_t)MKV_PAD * DD];
__device__ __half g_KV_h   [(size_t)MKV_PAD * 2048];
__device__ float  g_ln     [(size_t)MQ * DD];
__device__ __half g_lnr_h  [(size_t)MQ * DD];
__device__ __half g_Q_h    [(size_t)MQ * INNER];
__device__ __half g_O_h    [(size_t)MQ * INNER];
__device__ __half g_WkvT_h [(size_t)2048 * 1024];
__device__ __half g_WqT_h  [(size_t)1024 * 1024];
__device__ __half g_WoutT_h[(size_t)1024 * 1024];
__device__ float  g_dw     [NBT * HH];

__device__ __forceinline__ uint32_t smem_u32(const void* p)
{
    uint32_t a;
    asm("{ .reg .u64 t; cvta.to.shared.u64 t, %1; cvt.u32.u64 %0, t; }"
        : "=r"(a) : "l"(p));
    return a;
}

#define MMA_F16(d, a, b) \
    asm volatile( \
        "mma.sync.aligned.m16n8k16.row.col.f32.f16.f16.f32 " \
        "{%0,%1,%2,%3},{%4,%5,%6,%7},{%8,%9},{%0,%1,%2,%3};\n" \
        : "+f"((d)[0]), "+f"((d)[1]), "+f"((d)[2]), "+f"((d)[3]) \
        : "r"((a)[0]), "r"((a)[1]), "r"((a)[2]), "r"((a)[3]), \
          "r"((b)[0]), "r"((b)[1]))

#define MMA_F16B(d, a, b0, b1) \
    asm volatile( \
        "mma.sync.aligned.m16n8k16.row.col.f32.f16.f16.f32 " \
        "{%0,%1,%2,%3},{%4,%5,%6,%7},{%8,%9},{%0,%1,%2,%3};\n" \
        : "+f"((d)[0]), "+f"((d)[1]), "+f"((d)[2]), "+f"((d)[3]) \
        : "r"((a)[0]), "r"((a)[1]), "r"((a)[2]), "r"((a)[3]), \
          "r"(b0), "r"(b1))

#define LDMX4(r, addr) \
    asm volatile("ldmatrix.sync.aligned.m8n8.x4.shared.b16 {%0,%1,%2,%3}, [%4];" \
                 : "=r"((r)[0]), "=r"((r)[1]), "=r"((r)[2]), "=r"((r)[3]) \
                 : "r"(addr))

// ---------------------------------------------------------------------------
// LayerNorm (one 256-thread block per 1024-float row)
// ---------------------------------------------------------------------------
template<int MODE>
__global__ void ln_kernel(const float* __restrict__ in,
                          const float* __restrict__ gamma,
                          const float* __restrict__ beta)
{
    __shared__ float red[16];
    __shared__ float mu_s, rs_s;

    const int r   = blockIdx.x;
    const int tid = threadIdx.x;

    float4 v = reinterpret_cast<const float4*>(in + (size_t)r * DD)[tid];
    float s = v.x + v.y + v.z + v.w;
    float q = v.x * v.x + v.y * v.y + v.z * v.z + v.w * v.w;
#pragma unroll
    for (int o = 16; o > 0; o >>= 1) {
        s += __shfl_down_sync(0xffffffffu, s, o);
        q += __shfl_down_sync(0xffffffffu, q, o);
    }
    const int wid = tid >> 5;
    if ((tid & 31) == 0) { red[wid] = s; red[8 + wid] = q; }
    __syncthreads();
    if (tid == 0) {
        float ss = 0.f, qq = 0.f;
#pragma unroll
        for (int i = 0; i < 8; i++) { ss += red[i]; qq += red[8 + i]; }
        float mu  = ss * (1.0f / DD);
        float var = qq * (1.0f / DD) - mu * mu;
        mu_s = mu;
        rs_s = rsqrtf(var + 1e-5f);
    }
    __syncthreads();
    const float mu = mu_s, rs = rs_s;

    float4 gv = reinterpret_cast<const float4*>(gamma)[tid];
    float4 bv = reinterpret_cast<const float4*>(beta)[tid];
    float4 o;
    o.x = (v.x - mu) * rs * gv.x + bv.x;
    o.y = (v.y - mu) * rs * gv.y + bv.y;
    o.z = (v.z - mu) * rs * gv.z + bv.z;
    o.w = (v.w - mu) * rs * gv.w + bv.w;

    const __half2 h01 = __floats2half2_rn(o.x, o.y);
    const __half2 h23 = __floats2half2_rn(o.z, o.w);

    if (MODE == 1) {
        const int bt = r >> 10, i = r & 1023;
        __half2* d = reinterpret_cast<__half2*>(
            g_Akv_h + ((size_t)bt * NK + i) * DD) + 2 * tid;
        d[0] = h01; d[1] = h23;
    } else {
        reinterpret_cast<float4*>(g_ln + (size_t)r * DD)[tid] = o;
        __half2* dl = reinterpret_cast<__half2*>(g_lnr_h + (size_t)r * DD) + 2 * tid;
        dl[0] = h01; dl[1] = h23;
        const int bt = r >> 6, i = r & 63;
        if (i == 0) {
            __half2* da = reinterpret_cast<__half2*>(
                g_Akv_h + ((size_t)bt * NK + NN1) * DD) + 2 * tid;
            da[0] = h01; da[1] = h23;
        }
    }
}

// ---------------------------------------------------------------------------
// Transpose + fp16 convert (+scale): WT[n][k] = half(W[k][n] * scale)
// ---------------------------------------------------------------------------
__global__ void transpose_h(const float* __restrict__ W, __half* __restrict__ WT,
                            int Kd, int Nd, float scale)
{
    __shared__ float tile[32][33];
    const int n0 = blockIdx.x * 32, k0 = blockIdx.y * 32;
    const int tx = threadIdx.x, ty = threadIdx.y;
#pragma unroll
    for (int i = 0; i < 32; i += 8)
        tile[ty + i][tx] = W[(size_t)(k0 + ty + i) * Nd + n0 + tx];
    __syncthreads();
#pragma unroll
    for (int i = 0; i < 32; i += 8)
        WT[(size_t)(n0 + ty + i) * Kd + k0 + tx] =
            __float2half_rn(tile[tx][ty + i] * scale);
}

// ---------------------------------------------------------------------------
// fp16 GEMM: C[M,N] = A[M,K] * Bt[N,K]^T  (fp32 acc, OutT output)
// CTA 128x128, 256 thr, mma.m16n8k16, 4-stage cp.async ring, stride-40 smem
// pad, ldmatrix.x4 frag loads double-buffered across kk-steps and chunks.
// (R15 version — known-good: 402.5 us on kv GEMM, regs 124, tensor 56.7%.)
// ---------------------------------------------------------------------------
#define HCH   32
#define STG_BYTES (2 * 128 * 40 * 2)     // 20480 B
#define GEMM_H_SMEM (4 * STG_BYTES)      // 81920 B

template<typename OutT>
__global__ __launch_bounds__(256, 2)
void gemm_h(const __half* __restrict__ A, const __half* __restrict__ Bt,
            OutT* __restrict__ C, int M, int N, int K)
{
    extern __shared__ __half sh[];
    const uint32_t sb = smem_u32(sh);

    const int tid  = threadIdx.x;
    const int lane = tid & 31, warp = tid >> 5;
    const int g    = lane >> 2, tig = lane & 3;
    const int wm   = warp >> 2, wn = warp & 3;
    const int bm0  = blockIdx.y * 128, bn0 = blockIdx.x * 128;

    const int r0  = tid >> 2;
    const int sg0 = tid & 3;
    const __half* a_src = A  + (size_t)(bm0 + r0) * K + sg0 * 8;
    const __half* b_src = Bt + (size_t)(bn0 + r0) * K + sg0 * 8;
    const size_t rstep = (size_t)64 * K;
    const uint32_t soff = (uint32_t)(r0 * 80 + sg0 * 16);

    // ldmatrix lane offsets (bytes), rows are 80 B apart
    const uint32_t a_lm = (uint32_t)((wm * 64 + ((lane >> 3) & 1) * 8 + (lane & 7)) * 80
                                     + (lane >> 4) * 16);
    const uint32_t b_lm = (uint32_t)(128 * 80
                                     + (wn * 32 + ((lane >> 4) & 1) * 8 + (lane & 7)) * 80
                                     + ((lane >> 3) & 1) * 16);

    const int nch = K / HCH;

    auto load_chunk = [&](int c, int s) {
        const uint32_t abase = sb + s * STG_BYTES;
        const uint32_t bbase = abase + 128 * 80;
        const __half* ap = a_src + c * HCH;
        const __half* bp = b_src + c * HCH;
        asm volatile("cp.async.cg.shared.global [%0], [%1], 16;"
                     :: "r"(abase + soff),           "l"((const void*)ap) : "memory");
        asm volatile("cp.async.cg.shared.global [%0], [%1], 16;"
                     :: "r"(abase + soff + 64 * 80), "l"((const void*)(ap + rstep)) : "memory");
        asm volatile("cp.async.cg.shared.global [%0], [%1], 16;"
                     :: "r"(bbase + soff),           "l"((const void*)bp) : "memory");
        asm volatile("cp.async.cg.shared.global [%0], [%1], 16;"
                     :: "r"(bbase + soff + 64 * 80), "l"((const void*)(bp + rstep)) : "memory");
        asm volatile("cp.async.commit_group;" ::: "memory");
    };

    uint32_t af0[4][4], bf0[2][4];   // kk=0 fragments
    uint32_t af1[4][4], bf1[2][4];   // kk=1 fragments

    auto load_frags = [&](uint32_t stage, uint32_t koff,
                          uint32_t af[4][4], uint32_t bf[2][4]) {
#pragma unroll
        for (int mt = 0; mt < 4; mt++)
            LDMX4(af[mt], stage + a_lm + mt * 1280 + koff);
#pragma unroll
        for (int ntp = 0; ntp < 2; ntp++)
            LDMX4(bf[ntp], stage + b_lm + ntp * 1280 + koff);
    };

    float acc[4][4][4];
#pragma unroll
    for (int a = 0; a < 4; a++)
#pragma unroll
        for (int b = 0; b < 4; b++)
#pragma unroll
            for (int d = 0; d < 4; d++) acc[a][b][d] = 0.f;

    // prologue: fill 3 of 4 stages, then preload chunk 0 kk=0 fragments
    load_chunk(0, 0);
    load_chunk(1, 1);
    load_chunk(2, 2);
    asm volatile("cp.async.wait_group 2;" ::: "memory");   // chunk 0 resident
    __syncthreads();
    load_frags(sb, 0, af0, bf0);

    for (int c = 0; c < nch; c++) {
        // make chunk c+1 resident (chunk c already was)
        if (c + 1 < nch)
            asm volatile("cp.async.wait_group 1;" ::: "memory");
        else
            asm volatile("cp.async.wait_group 0;" ::: "memory");
        __syncthreads();   // all warps done reading stage (c+3)%4's previous chunk
        if (c + 3 < nch) load_chunk(c + 3, (c + 3) & 3);

        const uint32_t stage = sb + (c & 3) * STG_BYTES;

        // kk=0: prefetch kk=1 frags, then MMA on kk=0 frags
        load_frags(stage, 32, af1, bf1);
#pragma unroll
        for (int mt = 0; mt < 4; mt++)
#pragma unroll
            for (int nt = 0; nt < 4; nt++)
                MMA_F16B(acc[mt][nt], af0[mt],
                         bf0[nt >> 1][2 * (nt & 1)], bf0[nt >> 1][2 * (nt & 1) + 1]);

        // kk=1: prefetch next chunk's kk=0 frags, then MMA on kk=1 frags
        if (c + 1 < nch) {
            const uint32_t nstage = sb + ((c + 1) & 3) * STG_BYTES;
            load_frags(nstage, 0, af0, bf0);
        }
#pragma unroll
        for (int mt = 0; mt < 4; mt++)
#pragma unroll
            for (int nt = 0; nt < 4; nt++)
                MMA_F16B(acc[mt][nt], af1[mt],
                         bf1[nt >> 1][2 * (nt & 1)], bf1[nt >> 1][2 * (nt & 1) + 1]);
    }

#pragma unroll
    for (int mt = 0; mt < 4; mt++) {
        const int row = bm0 + wm * 64 + mt * 16 + g;
#pragma unroll
        for (int nt = 0; nt < 4; nt++) {
            const int col = bn0 + wn * 32 + nt * 8 + 2 * tig;
            if constexpr (sizeof(OutT) == 4) {
                *reinterpret_cast<float2*>((float*)C + (size_t)row * N + col) =
                    make_float2(acc[mt][nt][0], acc[mt][nt][1]);
                *reinterpret_cast<float2*>((float*)C + (size_t)(row + 8) * N + col) =
                    make_float2(acc[mt][nt][2], acc[mt][nt][3]);
            } else {
                *reinterpret_cast<__half2*>((__half*)C + (size_t)row * N + col) =
                    __floats2half2_rn(acc[mt][nt][0], acc[mt][nt][1]);
                *reinterpret_cast<__half2*>((__half*)C + (size_t)(row + 8) * N + col) =
                    __floats2half2_rn(acc[mt][nt][2], acc[mt][nt][3]);
            }
        }
    }
}

// ---------------------------------------------------------------------------
// dw = softmax(relu(mean(ln) @ Wd1 + bd1) @ Wd2 + bd2)
// ---------------------------------------------------------------------------
__global__ __launch_bounds__(256)
void dw_kernel(const float* __restrict__ Wd1, const float* __restrict__ bd1,
               const float* __restrict__ Wd2, const float* __restrict__ bd2)
{
    __shared__ float mean_s[1024];
    __shared__ float hid_s[256];
    const int bt  = blockIdx.x;
    const int tid = threadIdx.x;

    for (int d = tid; d < 1024; d += 256) {
        float s = 0.f;
#pragma unroll 4
        for (int r = 0; r < 64; r++)
            s += g_ln[((size_t)bt * 64 + r) * DD + d];
        mean_s[d] = s * (1.0f / 64.0f);
    }
    __syncthreads();

    float hsum = bd1[tid];
    for (int dd = 0; dd < 1024; dd++)
        hsum = fmaf(mean_s[dd], Wd1[dd * 256 + tid], hsum);
    hid_s[tid] = fmaxf(hsum, 0.f);
    __syncthreads();

    if (tid < 16) {
        float lg = bd2[tid];
        for (int j = 0; j < 256; j++)
            lg = fmaf(hid_s[j], Wd2[j * 16 + tid], lg);
        float mx = lg;
#pragma unroll
        for (int o = 8; o > 0; o >>= 1)
            mx = fmaxf(mx, __shfl_xor_sync(0x0000ffffu, mx, o));
        float e = expf(lg - mx);
        float ssum = e;
#pragma unroll
        for (int o = 8; o > 0; o >>= 1)
            ssum += __shfl_xor_sync(0x0000ffffu, ssum, o);
        g_dw[bt * HH + tid] = e / ssum;
    }
}

// ---------------------------------------------------------------------------
// Attention (tensor-core): one block per (bt,h), 128 threads (4 warps).
// K/V via 2-stage cp.async ring; masked tail keys zero-filled (then re-masked
// to -1e30, bit-identical to the blocking-load version).
// ---------------------------------------------------------------------------
#define AST 88                                   // smem stride in halves
#define QSZ (64 * AST)
#define KVSTG (2 * 64 * AST)                     // K + V per stage (halves)
#define ATTN_SMEM ((QSZ + 2 * KVSTG) * 2)        // 56320 B
#define LOG2E 1.4426950408889634f

__global__ __launch_bounds__(128)
void attn_kernel()
{
    extern __shared__ __half smh[];
    __half* Qs = smh;

    const int bt   = blockIdx.x >> 4;
    const int h    = blockIdx.x & 15;
    const int tid  = threadIdx.x;
    const int warp = tid >> 5, lane = tid & 31;
    const int g    = lane >> 2, tig = lane & 3;

    const uint32_t smb = smem_u32(smh);

    // async K/V chunk load into stage st (zero-fill beyond nk)
    auto load_kv = [&](int ch, int st) {
        const uint32_t ks = smb + (QSZ + st * KVSTG) * 2;
        const uint32_t vs = ks + 64 * AST * 2;
#pragma unroll
        for (int i = 0; i < 4; i++) {
            const int seg = tid + i * 128;
            const int j = seg >> 3, s = seg & 7;
            const int key = ch * 64 + j;
            const uint32_t nbytes = (key < NK) ? 16u : 0u;
            const int keyc = (key < NK) ? key : (NK - 1);
            const __half* kb = g_KV_h + ((size_t)bt * NK + keyc) * 2048
                             + h * DHH + s * 8;
            const uint32_t doff = (uint32_t)(j * AST + s * 8) * 2;
            asm volatile("cp.async.cg.shared.global [%0], [%1], 16, %2;"
                         :: "r"(ks + doff), "l"((const void*)kb), "r"(nbytes)
                         : "memory");
            asm volatile("cp.async.cg.shared.global [%0], [%1], 16, %2;"
                         :: "r"(vs + doff), "l"((const void*)(kb + INNER)), "r"(nbytes)
                         : "memory");
        }
        asm volatile("cp.async.commit_group;" ::: "memory");
    };

    // start chunk 0 early
    load_kv(0, 0);

    // load Q tile (64 x 64 fp16, pre-scaled via Wq)
#pragma unroll
    for (int i = 0; i < 4; i++) {
        const int seg = tid + i * 128;
        const int r = seg >> 3, s = seg & 7;
        uint4 v = *reinterpret_cast<const uint4*>(
            g_Q_h + ((size_t)bt * 64 + r) * INNER + h * DHH + s * 8);
        *reinterpret_cast<uint4*>(Qs + r * AST + s * 8) = v;
    }
    __syncthreads();

    // persistent Q A-fragments
    uint32_t qa[4][4];
    {
        const __half* q0 = Qs + (warp * 16 + g) * AST;
        const __half* q1 = q0 + 8 * AST;
#pragma unroll
        for (int u = 0; u < 4; u++) {
            const int k0 = u * 16 + 2 * tig;
            qa[u][0] = *reinterpret_cast<const uint32_t*>(q0 + k0);
            qa[u][1] = *reinterpret_cast<const uint32_t*>(q1 + k0);
            qa[u][2] = *reinterpret_cast<const uint32_t*>(q0 + k0 + 8);
            qa[u][3] = *reinterpret_cast<const uint32_t*>(q1 + k0 + 8);
        }
    }

    float acc[8][4];
#pragma unroll
    for (int d = 0; d < 8; d++)
#pragma unroll
        for (int j = 0; j < 4; j++) acc[d][j] = 0.f;
    float m0 = -1e30f, m1 = -1e30f, l0 = 0.f, l1 = 0.f;

    for (int ch = 0; ch < 17; ch++) {
        __syncthreads();   // prior iteration's K/V reads done before overwrite
        if (ch + 1 < 17) load_kv(ch + 1, (ch + 1) & 1);
        if (ch + 1 < 17)
            asm volatile("cp.async.wait_group 1;" ::: "memory");
        else
            asm volatile("cp.async.wait_group 0;" ::: "memory");
        __syncthreads();   // publish chunk ch

        __half* Ks = smh + QSZ + (ch & 1) * KVSTG;
        __half* Vs = Ks + 64 * AST;

        // S = Q @ K^T
        float sf[8][4];
#pragma unroll
        for (int t = 0; t < 8; t++) {
            sf[t][0] = sf[t][1] = sf[t][2] = sf[t][3] = 0.f;
            const __half* kr = Ks + (t * 8 + g) * AST + 2 * tig;
#pragma unroll
            for (int u = 0; u < 4; u++) {
                uint32_t bfr[2];
                bfr[0] = *reinterpret_cast<const uint32_t*>(kr + u * 16);
                bfr[1] = *reinterpret_cast<const uint32_t*>(kr + u * 16 + 8);
                MMA_F16(sf[t], qa[u], bfr);
            }
        }

        if (ch * 64 + 64 > NK) {
#pragma unroll
            for (int t = 0; t < 8; t++) {
                const int k0 = ch * 64 + t * 8 + 2 * tig;
                if (k0 >= NK)     { sf[t][0] = -1e30f; sf[t][2] = -1e30f; }
                if (k0 + 1 >= NK) { sf[t][1] = -1e30f; sf[t][3] = -1e30f; }
            }
        }

        // online softmax
        float mx0 = -1e30f, mx1 = -1e30f;
#pragma unroll
        for (int t = 0; t < 8; t++) {
            mx0 = fmaxf(mx0, fmaxf(sf[t][0], sf[t][1]));
            mx1 = fmaxf(mx1, fmaxf(sf[t][2], sf[t][3]));
        }
        mx0 = fmaxf(mx0, __shfl_xor_sync(0xffffffffu, mx0, 1));
        mx0 = fmaxf(mx0, __shfl_xor_sync(0xffffffffu, mx0, 2));
        mx1 = fmaxf(mx1, __shfl_xor_sync(0xffffffffu, mx1, 1));
        mx1 = fmaxf(mx1, __shfl_xor_sync(0xffffffffu, mx1, 2));

        const float mn0 = fmaxf(m0, mx0), mn1 = fmaxf(m1, mx1);
        const float corr0 = __expf(m0 - mn0), corr1 = __expf(m1 - mn1);
        m0 = mn0; m1 = mn1;

        uint32_t pa[8], pb[8];
        float sum0 = 0.f, sum1 = 0.f;
#pragma unroll
        for (int t = 0; t < 8; t++) {
            __half2 p01 = h2exp2(__floats2half2_rn((sf[t][0] - mn0) * LOG2E,
                                                   (sf[t][1] - mn0) * LOG2E));
            __half2 p23 = h2exp2(__floats2half2_rn((sf[t][2] - mn1) * LOG2E,
                                                   (sf[t][3] - mn1) * LOG2E));
            pa[t] = *reinterpret_cast<uint32_t*>(&p01);
            pb[t] = *reinterpret_cast<uint32_t*>(&p23);
            float2 f01 = __half22float2(p01);
            float2 f23 = __half22float2(p23);
            sum0 += f01.x + f01.y;
            sum1 += f23.x + f23.y;
        }
        sum0 += __shfl_xor_sync(0xffffffffu, sum0, 1);
        sum0 += __shfl_xor_sync(0xffffffffu, sum0, 2);
        sum1 += __shfl_xor_sync(0xffffffffu, sum1, 1);
        sum1 += __shfl_xor_sync(0xffffffffu, sum1, 2);
        l0 = l0 * corr0 + sum0;
        l1 = l1 * corr1 + sum1;

#pragma unroll
        for (int d = 0; d < 8; d++) {
            acc[d][0] *= corr0; acc[d][1] *= corr0;
            acc[d][2] *= corr1; acc[d][3] *= corr1;
        }

        // O += P @ V
#pragma unroll
        for (int u = 0; u < 4; u++) {
            uint32_t pf[4] = { pa[2 * u], pb[2 * u], pa[2 * u + 1], pb[2 * u + 1] };
            const uint32_t vaddr = smem_u32(Vs + (u * 16 + (lane & 15)) * AST);
#pragma unroll
            for (int d = 0; d < 8; d++) {
                uint32_t bfr[2];
                asm volatile(
                    "ldmatrix.sync.aligned.m8n8.x2.trans.shared.b16 {%0,%1}, [%2];"
                    : "=r"(bfr[0]), "=r"(bfr[1]) : "r"(vaddr + d * 16));
                MMA_F16(acc[d], pf, bfr);
            }
        }
    }

    const float dwv = g_dw[bt * HH + h];
    const float sc0 = dwv / l0, sc1 = dwv / l1;
    const size_t row0 = (size_t)bt * 64 + warp * 16 + g;
#pragma unroll
    for (int d = 0; d < 8; d++) {
        const int col = h * DHH + d * 8 + 2 * tig;
        *reinterpret_cast<__half2*>(g_O_h + row0 * INNER + col) =
            __floats2half2_rn(acc[d][0] * sc0, acc[d][1] * sc0);
        *reinterpret_cast<__half2*>(g_O_h + (row0 + 8) * INNER + col) =
            __floats2half2_rn(acc[d][2] * sc1, acc[d][3] * sc1);
    }
}

// ---------------------------------------------------------------------------
extern "C" void kernel_launch(void* const* d_in, const int* in_sizes, int n_in,
                              void* d_out, int out_size)
{
    const float* x       = (const float*)d_in[0];
    const float* latents = (const float*)d_in[1];
    const float* gm      = (const float*)d_in[2];
    const float* bm      = (const float*)d_in[3];
    const float* gl      = (const float*)d_in[4];
    const float* bl      = (const float*)d_in[5];
    const float* Wq      = (const float*)d_in[6];
    const float* Wkv     = (const float*)d_in[7];
    const float* Wout    = (const float*)d_in[8];
    const float* Wd1     = (const float*)d_in[9];
    const float* bd1     = (const float*)d_in[10];
    const float* Wd2     = (const float*)d_in[11];
    const float* bd2     = (const float*)d_in[12];
    float* out = (float*)d_out;

    cudaFuncSetAttribute(gemm_h<__half>,
        cudaFuncAttributeMaxDynamicSharedMemorySize, GEMM_H_SMEM);
    cudaFuncSetAttribute(gemm_h<float>,
        cudaFuncAttributeMaxDynamicSharedMemorySize, GEMM_H_SMEM);
    cudaFuncSetAttribute(attn_kernel,
        cudaFuncAttributeMaxDynamicSharedMemorySize, ATTN_SMEM);

    __half *p_Akv, *p_lnr, *p_Q, *p_O, *p_KV, *p_WkvT, *p_WqT, *p_WoutT;
    cudaGetSymbolAddress((void**)&p_Akv,   g_Akv_h);
    cudaGetSymbolAddress((void**)&p_lnr,   g_lnr_h);
    cudaGetSymbolAddress((void**)&p_Q,     g_Q_h);
    cudaGetSymbolAddress((void**)&p_O,     g_O_h);
    cudaGetSymbolAddress((void**)&p_KV,    g_KV_h);
    cudaGetSymbolAddress((void**)&p_WkvT,  g_WkvT_h);
    cudaGetSymbolAddress((void**)&p_WqT,   g_WqT_h);
    cudaGetSymbolAddress((void**)&p_WoutT, g_WoutT_h);

    // Order keeps kv GEMM at ncu's profiled launch slot (index 3).
    transpose_h<<<dim3(64, 32), dim3(32, 8)>>>(Wkv,  p_WkvT,  1024, 2048, 1.0f);
    ln_kernel<1><<<BB * TT * NN1, 256>>>(x, gm, bm);
    ln_kernel<0><<<BB * TT * NN2, 256>>>(latents, gl, bl);

    // KV = Akv @ Wkv   (fp16 out)
    gemm_h<__half><<<dim3(16, MKV_PAD / 128), 256, GEMM_H_SMEM>>>(
        p_Akv, p_WkvT, p_KV, MKV_PAD, 2048, 1024);

    transpose_h<<<dim3(32, 32), dim3(32, 8)>>>(Wq,   p_WqT,   1024, 1024, 0.125f);
    transpose_h<<<dim3(32, 32), dim3(32, 8)>>>(Wout, p_WoutT, 1024, 1024, 1.0f);

    // Q = lnr @ (0.125*Wq)  (fp16 out)
    gemm_h<__half><<<dim3(8, 16), 256, GEMM_H_SMEM>>>(
        p_lnr, p_WqT, p_Q, MQ, 1024, 1024);

    // dynamic head weights
    dw_kernel<<<NBT, 256>>>(Wd1, bd1, Wd2, bd2);

    // attention (tensor cores)
    attn_kernel<<<NBT * HH, 128, ATTN_SMEM>>>();

    // out = O @ Wout   (fp32 out)
    gemm_h<float><<<dim3(8, 16), 256, GEMM_H_SMEM>>>(
        p_O, p_WoutT, out, MQ, 1024, 1024);
}